// round 6
// baseline (speedup 1.0000x reference)
#include <cuda_runtime.h>
#include <cuda_bf16.h>
#include <float.h>
#include <math.h>
#include <stdint.h>

// ---------------- problem constants ----------------
constexpr int   Bn   = 16;
constexpr int   Nn   = 33600;
constexpr int   Cc   = 80;
constexpr int   MAXN = 100;
constexpr float THR  = 0.05f;
constexpr float IOUT = 0.65f;

// histogram constants: bucket = (bits - BASE) >> 14
constexpr unsigned BASE   = 0x3D000000u;            // below bits(0.05)=0x3D4CCCCD
constexpr int      HB     = 2560;                   // (0x3F800000-BASE)>>14
constexpr int      HBPAD  = 3072;                   // padded to 1024*3 for the scan
constexpr int      CHUNKB = 3;                      // buckets per scan thread
constexpr int      CAP    = 1024;                   // candidate capacity
constexpr int      SLICES = 8;                      // hist CTAs per batch

// ---------------- device scratch ----------------
__device__ float    g_scores[Bn * Nn];    // masked score: s if s>=THR else -FLT_MAX
__device__ int      g_labels[Bn * Nn];    // argmax class
__device__ unsigned g_hist[Bn * HBPAD];   // per-batch score-bit histogram (padded)

// ---------------- kernel 0: zero the histogram ----------------
__global__ void k_zero() {
    int i = blockIdx.x * blockDim.x + threadIdx.x;
    if (i < Bn * HBPAD) g_hist[i] = 0u;
}

// ---------------- kernel 1: sigmoid + max/argmax + score ----------------
__global__ void k_score(const float* __restrict__ cls,
                        const float* __restrict__ obj) {
    int t   = blockIdx.x * blockDim.x + threadIdx.x;
    int a   = t >> 2;
    int sub = t & 3;
    if (a >= Bn * Nn) return;

    const float4* p = reinterpret_cast<const float4*>(cls + (size_t)a * Cc + sub * 20);
    float mx = -FLT_MAX;
    int   mi = 0;
#pragma unroll
    for (int i = 0; i < 5; i++) {
        float4 v = p[i];
        int base = sub * 20 + i * 4;
        if (v.x > mx) { mx = v.x; mi = base; }
        if (v.y > mx) { mx = v.y; mi = base + 1; }
        if (v.z > mx) { mx = v.z; mi = base + 2; }
        if (v.w > mx) { mx = v.w; mi = base + 3; }
    }
#pragma unroll
    for (int off = 1; off < 4; off <<= 1) {
        float om  = __shfl_xor_sync(0xffffffffu, mx, off);
        int   omi = __shfl_xor_sync(0xffffffffu, mi, off);
        if (om > mx || (om == mx && omi < mi)) { mx = om; mi = omi; }
    }
    if (sub == 0) {
        float o = obj[a];
        float s = (1.0f / (1.0f + __expf(-mx))) * (1.0f / (1.0f + __expf(-o)));
        g_scores[a] = (s >= THR) ? s : -FLT_MAX;
        g_labels[a] = mi;
    }
}

// ---------------- kernel 1b: global histogram, 8 CTAs per batch ----------------
constexpr int SLICE_Q = Nn / 4 / SLICES;   // float4s per slice = 1050

__global__ void k_hist() {
    int b = blockIdx.x / SLICES;
    int s = blockIdx.x % SLICES;
    const float4* sp = reinterpret_cast<const float4*>(g_scores + (size_t)b * Nn)
                       + s * SLICE_Q;
    unsigned* hh = g_hist + b * HBPAD;

    for (int i = threadIdx.x; i < SLICE_Q; i += blockDim.x) {
        float4 v = sp[i];
        if (v.x >= THR) atomicAdd(&hh[(__float_as_uint(v.x) - BASE) >> 14], 1u);
        if (v.y >= THR) atomicAdd(&hh[(__float_as_uint(v.y) - BASE) >> 14], 1u);
        if (v.z >= THR) atomicAdd(&hh[(__float_as_uint(v.z) - BASE) >> 14], 1u);
        if (v.w >= THR) atomicAdd(&hh[(__float_as_uint(v.w) - BASE) >> 14], 1u);
    }
}

// intra-warp inclusive suffix sum (sum over lanes [lane..31])
__device__ __forceinline__ unsigned warp_suffix_sum(unsigned v, int lane) {
#pragma unroll
    for (int o = 1; o < 32; o <<= 1) {
        unsigned u = __shfl_down_sync(0xffffffffu, v, o);
        if (lane + o < 32) v += u;
    }
    return v;
}

// ---------------- kernel 2: threshold scan + compact + rank + decode + NMS ----------------
__global__ void __launch_bounds__(1024, 1)
k_select_nms(const float* __restrict__ bbox,
             const float* __restrict__ priors,
             float* __restrict__ out,
             int write_keep) {
    __shared__ unsigned           csum[1024];
    __shared__ unsigned           wsum[32];
    __shared__ unsigned long long cand[CAP];
    __shared__ unsigned long long sorted[128];
    __shared__ int                misc[2];
    __shared__ float4             bx4[128];
    __shared__ float              ars[128];
    __shared__ int                lls[128];

    int b    = blockIdx.x;
    int tid  = threadIdx.x;
    int lane = tid & 31;
    int wid  = tid >> 5;
    const float*    sc = g_scores + (size_t)b * Nn;
    const unsigned* hh = g_hist + b * HBPAD;

    // --- A: chunk sums (3 buckets per thread) ---
    unsigned cs = 0;
#pragma unroll
    for (int i = 0; i < CHUNKB; i++) cs += hh[tid * CHUNKB + i];

    // --- B: parallel suffix scan over 1024 chunk sums ---
    unsigned suf = warp_suffix_sum(cs, lane);
    if (lane == 0) wsum[wid] = suf;
    if (tid == 0) misc[0] = 0;
    __syncthreads();
    if (wid == 0) {
        unsigned wv = wsum[lane];
        wsum[lane] = warp_suffix_sum(wv, lane);
    }
    __syncthreads();
    unsigned suffTotal = suf + ((wid < 31) ? wsum[wid + 1] : 0u);
    csum[tid] = suffTotal;
    __syncthreads();

    // boundary chunk: suffix(c) >= MAXN and suffix(c+1) < MAXN
    if (suffTotal >= (unsigned)MAXN &&
        (tid == 1023 || csum[tid + 1] < (unsigned)MAXN))
        misc[0] = tid;
    __syncthreads();

    // --- C: refine to bucket within boundary chunk (<=3 serial steps) ---
    if (tid == 0) {
        int c = misc[0];
        int cum = (c < 1023) ? (int)csum[c + 1] : 0;
        int bstart = c * CHUNKB;
        int bb = bstart + CHUNKB - 1;
        for (; bb >= bstart; bb--) {
            cum += (int)hh[bb];
            if (cum >= MAXN) break;
        }
        misc[0] = (bb < bstart) ? bstart : bb;   // total<MAXN -> take everything
        misc[1] = 0;
    }
    __syncthreads();

    // --- D: compact candidates >= bucket boundary (float4 loads, high MLP) ---
    unsigned TB = BASE + ((unsigned)misc[0] << 14);
    const float4* sp4 = reinterpret_cast<const float4*>(sc);
#pragma unroll 2
    for (int i = tid; i < Nn / 4; i += 1024) {
        float4 v = sp4[i];
        unsigned bx_ = __float_as_uint(v.x);
        unsigned by_ = __float_as_uint(v.y);
        unsigned bz_ = __float_as_uint(v.z);
        unsigned bw_ = __float_as_uint(v.w);
        if (v.x >= THR && bx_ >= TB) {
            int pos = atomicAdd(&misc[1], 1);
            if (pos < CAP) cand[pos] = ((unsigned long long)bx_ << 32) | (unsigned)(~(4 * i + 0));
        }
        if (v.y >= THR && by_ >= TB) {
            int pos = atomicAdd(&misc[1], 1);
            if (pos < CAP) cand[pos] = ((unsigned long long)by_ << 32) | (unsigned)(~(4 * i + 1));
        }
        if (v.z >= THR && bz_ >= TB) {
            int pos = atomicAdd(&misc[1], 1);
            if (pos < CAP) cand[pos] = ((unsigned long long)bz_ << 32) | (unsigned)(~(4 * i + 2));
        }
        if (v.w >= THR && bw_ >= TB) {
            int pos = atomicAdd(&misc[1], 1);
            if (pos < CAP) cand[pos] = ((unsigned long long)bw_ << 32) | (unsigned)(~(4 * i + 3));
        }
    }
    __syncthreads();
    int cnt = misc[1]; if (cnt > CAP) cnt = CAP;

    // --- E: exact ordering by rank (keys unique: idx in low bits) ---
    if (tid < 128) sorted[tid] = 0ull;
    unsigned long long mykey = 0ull;
    int rank = 0;
    if (tid < cnt) {
        mykey = cand[tid];
#pragma unroll 4
        for (int j = 0; j < cnt; j++) rank += (cand[j] > mykey);
    }
    __syncthreads();
    if (tid < cnt && rank < 128) sorted[rank] = mykey;
    __syncthreads();

    // --- F: warp 0 only: decode top-100 + greedy class-aware NMS + write ---
    if (wid != 0) return;

    float x1q[4], y1q[4], x2q[4], y2q[4], aq[4], sq[4];
    int   lq[4];
    unsigned kmask = 0;
#pragma unroll
    for (int q = 0; q < 4; q++) {
        int r = lane + 32 * q;
        x1q[q] = y1q[q] = x2q[q] = y2q[q] = aq[q] = sq[q] = 0.0f;
        lq[q] = -1;
        if (r < MAXN) {
            unsigned long long key = sorted[r];
            unsigned bits = (unsigned)(key >> 32);
            if (bits != 0u) {
                int idx = (int)(~(unsigned)(key & 0xffffffffu));
                float4 pr = reinterpret_cast<const float4*>(priors)[idx];
                float4 bp = reinterpret_cast<const float4*>(bbox)[(size_t)b * Nn + idx];
                float cx = bp.x * pr.z + pr.x;
                float cy = bp.y * pr.w + pr.y;
                float w  = __expf(bp.z) * pr.z;
                float h  = __expf(bp.w) * pr.w;
                x1q[q] = cx - 0.5f * w; y1q[q] = cy - 0.5f * h;
                x2q[q] = cx + 0.5f * w; y2q[q] = cy + 0.5f * h;
                aq[q]  = w * h;
                sq[q]  = __uint_as_float(bits);
                lq[q]  = g_labels[(size_t)b * Nn + idx];
                kmask |= (1u << q);
            }
        }
    }
#pragma unroll
    for (int q = 0; q < 4; q++) {
        int r = lane + 32 * q;
        if (r < MAXN) {
            bx4[r] = make_float4(x1q[q], y1q[q], x2q[q], y2q[q]);
            ars[r] = aq[q];
            lls[r] = lq[q];
        }
    }
    __syncwarp();

    for (int i = 0; i < MAXN - 1; i++) {
        unsigned km = __shfl_sync(0xffffffffu, kmask, i & 31);
        bool kpi = (km >> (i >> 5)) & 1u;
        float4 bi = bx4[i];
        float  ai = ars[i];
        int    li = lls[i];
        if (kpi) {
#pragma unroll
            for (int q = 0; q < 4; q++) {
                int r = lane + 32 * q;
                if (((kmask >> q) & 1u) && r > i && lq[q] == li) {
                    float ix1 = fmaxf(x1q[q], bi.x);
                    float iy1 = fmaxf(y1q[q], bi.y);
                    float ix2 = fminf(x2q[q], bi.z);
                    float iy2 = fminf(y2q[q], bi.w);
                    float inter = fmaxf(ix2 - ix1, 0.0f) * fmaxf(iy2 - iy1, 0.0f);
                    float uni   = aq[q] + ai - inter;
                    if (inter / (uni + 1e-8f) >= IOUT) kmask &= ~(1u << q);
                }
            }
        }
        __syncwarp();
    }

#pragma unroll
    for (int q = 0; q < 4; q++) {
        int r = lane + 32 * q;
        if (r < MAXN) {
            float* row = out + ((size_t)b * MAXN + r) * 6;
            bool kept = (kmask >> q) & 1u;
            if (kept) {
                row[0] = x1q[q]; row[1] = y1q[q];
                row[2] = x2q[q]; row[3] = y2q[q];
                row[4] = sq[q];  row[5] = (float)lq[q];
            } else {
                row[0] = 0.0f; row[1] = 0.0f; row[2] = 0.0f; row[3] = 0.0f;
                row[4] = 0.0f; row[5] = -1.0f;
            }
            if (write_keep)
                out[(size_t)Bn * MAXN * 6 + b * MAXN + r] = kept ? 1.0f : 0.0f;
        }
    }
}

// ---------------- host launcher ----------------
extern "C" void kernel_launch(void* const* d_in, const int* in_sizes, int n_in,
                              void* d_out, int out_size) {
    const float* cls    = nullptr;
    const float* bbox   = nullptr;
    const float* obj    = nullptr;
    const float* priors = nullptr;
    for (int i = 0; i < n_in; i++) {
        int sz = in_sizes[i];
        if      (sz == Bn * Nn * Cc) cls    = (const float*)d_in[i];
        else if (sz == Bn * Nn * 4)  bbox   = (const float*)d_in[i];
        else if (sz == Bn * Nn)      obj    = (const float*)d_in[i];
        else if (sz == Nn * 4)       priors = (const float*)d_in[i];
    }
    float* out = (float*)d_out;
    int write_keep = (out_size >= Bn * MAXN * 6 + Bn * MAXN) ? 1 : 0;

    k_zero<<<(Bn * HBPAD + 255) / 256, 256>>>();
    int total_threads = Bn * Nn * 4;
    k_score<<<(total_threads + 255) / 256, 256>>>(cls, obj);
    k_hist<<<Bn * SLICES, 256>>>();
    k_select_nms<<<Bn, 1024>>>(bbox, priors, out, write_keep);
}

// round 7
// speedup vs baseline: 1.2584x; 1.2584x over previous
#include <cuda_runtime.h>
#include <cuda_bf16.h>
#include <float.h>
#include <math.h>
#include <stdint.h>

// ---------------- problem constants ----------------
constexpr int   Bn   = 16;
constexpr int   Nn   = 33600;
constexpr int   Cc   = 80;
constexpr int   MAXN = 100;
constexpr float THR  = 0.05f;
constexpr float IOUT = 0.65f;

// histogram constants: bucket = (bits - BASE) >> 14
constexpr unsigned BASE   = 0x3D000000u;   // below bits(0.05)=0x3D4CCCCD
constexpr int      HB     = 2560;          // (0x3F800000-BASE)>>14
constexpr int      HBPAD  = 3072;          // padded to 1024*3 for the scan
constexpr int      CHUNKB = 3;             // buckets per scan thread
constexpr int      CAP    = 1024;          // candidate capacity

// ---------------- device scratch ----------------
__device__ float              g_scores[Bn * Nn];     // masked score (-FLT_MAX if < THR)
__device__ int                g_labels[Bn * Nn];     // argmax class
__device__ unsigned           g_hist[Bn * HBPAD];    // zero-init; re-zeroed by k_select
__device__ unsigned long long g_sorted[Bn * 128];    // exact-ordered top keys (0 = invalid)

// ---------------- kernel 1: sigmoid + max/argmax + score + fused RED histogram ----------------
__global__ void k_score(const float* __restrict__ cls,
                        const float* __restrict__ obj) {
    int t   = blockIdx.x * blockDim.x + threadIdx.x;
    int a   = t >> 1;          // anchor
    int sub = t & 1;           // half (40 classes each)
    if (a >= Bn * Nn) return;

    const float4* p = reinterpret_cast<const float4*>(cls + (size_t)a * Cc + sub * 40);
    float mx = -FLT_MAX;
    int   mi = 0;
#pragma unroll
    for (int i = 0; i < 10; i++) {
        float4 v = p[i];
        int base = sub * 40 + i * 4;
        if (v.x > mx) { mx = v.x; mi = base; }
        if (v.y > mx) { mx = v.y; mi = base + 1; }
        if (v.z > mx) { mx = v.z; mi = base + 2; }
        if (v.w > mx) { mx = v.w; mi = base + 3; }
    }
    {   // pairwise reduce across the 2 lanes of this anchor (tie -> smaller idx)
        float om  = __shfl_xor_sync(0xffffffffu, mx, 1);
        int   omi = __shfl_xor_sync(0xffffffffu, mi, 1);
        if (om > mx || (om == mx && omi < mi)) { mx = om; mi = omi; }
    }
    if (sub == 0) {
        float o = obj[a];
        float s = (1.0f / (1.0f + __expf(-mx))) * (1.0f / (1.0f + __expf(-o)));
        if (s >= THR) {
            unsigned bits = __float_as_uint(s);
            unsigned bk   = (bits - BASE) >> 14;
            if (bk >= (unsigned)HB) bk = HB - 1;
            int batch = a / Nn;
            atomicAdd(&g_hist[batch * HBPAD + bk], 1u);   // RED (no return), chip-wide
            g_scores[a] = s;
        } else {
            g_scores[a] = -FLT_MAX;
        }
        g_labels[a] = mi;
    }
}

// intra-warp inclusive suffix sum (sum over lanes [lane..31])
__device__ __forceinline__ unsigned warp_suffix_sum(unsigned v, int lane) {
#pragma unroll
    for (int o = 1; o < 32; o <<= 1) {
        unsigned u = __shfl_down_sync(0xffffffffu, v, o);
        if (lane + o < 32) v += u;
    }
    return v;
}

// ---------------- kernel 2: threshold scan + hist re-zero + compact + exact rank ----------------
__global__ void __launch_bounds__(1024, 1)
k_select(int dummy) {
    __shared__ unsigned           csum[1024];
    __shared__ unsigned           wsum[32];
    __shared__ unsigned long long cand[CAP];
    __shared__ unsigned long long sorted[128];
    __shared__ int                misc[2];

    int b    = blockIdx.x;
    int tid  = threadIdx.x;
    int lane = tid & 31;
    int wid  = tid >> 5;
    const float* sc = g_scores + (size_t)b * Nn;
    unsigned*    hh = g_hist + b * HBPAD;

    // --- A: chunk sums (3 buckets per thread) ---
    unsigned h0 = hh[tid * CHUNKB + 0];
    unsigned h1 = hh[tid * CHUNKB + 1];
    unsigned h2 = hh[tid * CHUNKB + 2];
    unsigned cs = h0 + h1 + h2;

    // --- B: parallel suffix scan over 1024 chunk sums ---
    unsigned suf = warp_suffix_sum(cs, lane);
    if (lane == 0) wsum[wid] = suf;
    if (tid == 0) misc[0] = 0;
    __syncthreads();
    if (wid == 0) {
        unsigned wv = wsum[lane];
        wsum[lane] = warp_suffix_sum(wv, lane);
    }
    __syncthreads();
    unsigned suffTotal = suf + ((wid < 31) ? wsum[wid + 1] : 0u);
    csum[tid] = suffTotal;
    __syncthreads();

    // boundary chunk: suffix(c) >= MAXN and suffix(c+1) < MAXN
    if (suffTotal >= (unsigned)MAXN &&
        (tid == 1023 || csum[tid + 1] < (unsigned)MAXN))
        misc[0] = tid;
    __syncthreads();

    // --- C: refine to bucket within boundary chunk (<=3 serial steps) ---
    if (tid == 0) {
        int c = misc[0];
        int cum = (c < 1023) ? (int)csum[c + 1] : 0;
        int bstart = c * CHUNKB;
        int bb = bstart + CHUNKB - 1;
        for (; bb >= bstart; bb--) {
            cum += (int)hh[bb];
            if (cum >= MAXN) break;
        }
        misc[0] = (bb < bstart) ? bstart : bb;   // total<MAXN -> take everything
        misc[1] = 0;
    }
    __syncthreads();
    unsigned TB = BASE + ((unsigned)misc[0] << 14);

    // re-zero this batch's histogram for the next graph replay
    hh[tid * CHUNKB + 0] = 0u;
    hh[tid * CHUNKB + 1] = 0u;
    hh[tid * CHUNKB + 2] = 0u;

    // --- D: compact candidates >= bucket boundary (float4 loads) ---
    const float4* sp4 = reinterpret_cast<const float4*>(sc);
#pragma unroll 2
    for (int i = tid; i < Nn / 4; i += 1024) {
        float4 v = sp4[i];
        unsigned bx_ = __float_as_uint(v.x);
        unsigned by_ = __float_as_uint(v.y);
        unsigned bz_ = __float_as_uint(v.z);
        unsigned bw_ = __float_as_uint(v.w);
        if (v.x >= THR && bx_ >= TB) {
            int pos = atomicAdd(&misc[1], 1);
            if (pos < CAP) cand[pos] = ((unsigned long long)bx_ << 32) | (unsigned)(~(4 * i + 0));
        }
        if (v.y >= THR && by_ >= TB) {
            int pos = atomicAdd(&misc[1], 1);
            if (pos < CAP) cand[pos] = ((unsigned long long)by_ << 32) | (unsigned)(~(4 * i + 1));
        }
        if (v.z >= THR && bz_ >= TB) {
            int pos = atomicAdd(&misc[1], 1);
            if (pos < CAP) cand[pos] = ((unsigned long long)bz_ << 32) | (unsigned)(~(4 * i + 2));
        }
        if (v.w >= THR && bw_ >= TB) {
            int pos = atomicAdd(&misc[1], 1);
            if (pos < CAP) cand[pos] = ((unsigned long long)bw_ << 32) | (unsigned)(~(4 * i + 3));
        }
    }
    __syncthreads();
    int cnt = misc[1]; if (cnt > CAP) cnt = CAP;

    // --- E: exact ordering by rank (keys unique: idx in low bits) ---
    if (tid < 128) sorted[tid] = 0ull;
    unsigned long long mykey = 0ull;
    int rank = 0;
    if (tid < cnt) {
        mykey = cand[tid];
#pragma unroll 4
        for (int j = 0; j < cnt; j++) rank += (cand[j] > mykey);
    }
    __syncthreads();
    if (tid < cnt && rank < 128) sorted[rank] = mykey;
    __syncthreads();
    if (tid < 128) g_sorted[b * 128 + tid] = sorted[tid];
}

// ---------------- kernel 3: decode + parallel suppression matrix + bit-scan NMS ----------------
__global__ void __launch_bounds__(256, 1)
k_nms(const float* __restrict__ bbox,
      const float* __restrict__ priors,
      float* __restrict__ out,
      int write_keep) {
    __shared__ float4   bx4[MAXN];
    __shared__ float    ars[MAXN];
    __shared__ float    sss[MAXN];
    __shared__ int      lls[MAXN];
    __shared__ unsigned sup[MAXN][4];   // sup[i][w]: bits r that box-i suppresses
    __shared__ unsigned kin[4];         // initial keep (valid) bitmask
    __shared__ unsigned kout[4];        // final keep bitmask

    int b   = blockIdx.x;
    int tid = threadIdx.x;

    if (tid < 4) { kin[tid] = 0u; }
    if (tid < MAXN) { sup[tid][0] = 0u; sup[tid][1] = 0u; sup[tid][2] = 0u; sup[tid][3] = 0u; }

    if (tid < MAXN) {
        unsigned long long key = g_sorted[b * 128 + tid];
        unsigned bits = (unsigned)(key >> 32);
        if (bits != 0u) {
            int idx = (int)(~(unsigned)(key & 0xffffffffu));
            float4 pr = reinterpret_cast<const float4*>(priors)[idx];
            float4 bp = reinterpret_cast<const float4*>(bbox)[(size_t)b * Nn + idx];
            float cx = bp.x * pr.z + pr.x;
            float cy = bp.y * pr.w + pr.y;
            float w  = __expf(bp.z) * pr.z;
            float h  = __expf(bp.w) * pr.w;
            bx4[tid] = make_float4(cx - 0.5f * w, cy - 0.5f * h,
                                   cx + 0.5f * w, cy + 0.5f * h);
            ars[tid] = w * h;
            sss[tid] = __uint_as_float(bits);
            lls[tid] = g_labels[(size_t)b * Nn + idx];
            atomicOr(&kin[tid >> 5], 1u << (tid & 31));
        } else {
            bx4[tid] = make_float4(0.f, 0.f, 0.f, 0.f);
            ars[tid] = 0.f; sss[tid] = 0.f; lls[tid] = -1;
        }
    }
    __syncthreads();

    // parallel pairwise suppression bits (r > i, same label, IoU >= thr)
    for (int p = tid; p < MAXN * MAXN; p += 256) {
        int i = p / MAXN;
        int r = p - i * MAXN;
        if (r > i) {
            int li = lls[i];
            if (li >= 0 && li == lls[r]) {
                float4 bi = bx4[i];
                float4 br = bx4[r];
                float ix1 = fmaxf(br.x, bi.x);
                float iy1 = fmaxf(br.y, bi.y);
                float ix2 = fminf(br.z, bi.z);
                float iy2 = fminf(br.w, bi.w);
                float inter = fmaxf(ix2 - ix1, 0.0f) * fmaxf(iy2 - iy1, 0.0f);
                float uni   = ars[i] + ars[r] - inter;
                if (inter / (uni + 1e-8f) >= IOUT)
                    atomicOr(&sup[i][r >> 5], 1u << (r & 31));
            }
        }
    }
    __syncthreads();

    // greedy scan: pure register bit logic on one thread
    if (tid == 0) {
        unsigned k0 = kin[0], k1 = kin[1], k2 = kin[2], k3 = kin[3];
#pragma unroll 4
        for (int i = 0; i < MAXN - 1; i++) {
            unsigned kw = (i < 32) ? k0 : (i < 64) ? k1 : (i < 96) ? k2 : k3;
            if ((kw >> (i & 31)) & 1u) {
                k0 &= ~sup[i][0];
                k1 &= ~sup[i][1];
                k2 &= ~sup[i][2];
                k3 &= ~sup[i][3];
            }
        }
        kout[0] = k0; kout[1] = k1; kout[2] = k2; kout[3] = k3;
    }
    __syncthreads();

    if (tid < MAXN) {
        bool kept = (kout[tid >> 5] >> (tid & 31)) & 1u;
        float* row = out + ((size_t)b * MAXN + tid) * 6;
        if (kept) {
            float4 bb = bx4[tid];
            row[0] = bb.x; row[1] = bb.y; row[2] = bb.z; row[3] = bb.w;
            row[4] = sss[tid]; row[5] = (float)lls[tid];
        } else {
            row[0] = 0.0f; row[1] = 0.0f; row[2] = 0.0f; row[3] = 0.0f;
            row[4] = 0.0f; row[5] = -1.0f;
        }
        if (write_keep)
            out[(size_t)Bn * MAXN * 6 + b * MAXN + tid] = kept ? 1.0f : 0.0f;
    }
}

// ---------------- host launcher ----------------
extern "C" void kernel_launch(void* const* d_in, const int* in_sizes, int n_in,
                              void* d_out, int out_size) {
    const float* cls    = nullptr;
    const float* bbox   = nullptr;
    const float* obj    = nullptr;
    const float* priors = nullptr;
    for (int i = 0; i < n_in; i++) {
        int sz = in_sizes[i];
        if      (sz == Bn * Nn * Cc) cls    = (const float*)d_in[i];
        else if (sz == Bn * Nn * 4)  bbox   = (const float*)d_in[i];
        else if (sz == Bn * Nn)      obj    = (const float*)d_in[i];
        else if (sz == Nn * 4)       priors = (const float*)d_in[i];
    }
    float* out = (float*)d_out;
    int write_keep = (out_size >= Bn * MAXN * 6 + Bn * MAXN) ? 1 : 0;

    int total_threads = Bn * Nn * 2;
    k_score<<<(total_threads + 255) / 256, 256>>>(cls, obj);
    k_select<<<Bn, 1024>>>(0);
    k_nms<<<Bn, 256>>>(bbox, priors, out, write_keep);
}

// round 8
// speedup vs baseline: 1.4467x; 1.1497x over previous
#include <cuda_runtime.h>
#include <cuda_bf16.h>
#include <float.h>
#include <math.h>
#include <stdint.h>

// ---------------- problem constants ----------------
constexpr int   Bn   = 16;
constexpr int   Nn   = 33600;
constexpr int   Cc   = 80;
constexpr int   MAXN = 100;
constexpr float THR  = 0.05f;
constexpr float IOUT = 0.65f;

// histogram constants: bucket = (bits - BASE) >> 14
constexpr unsigned BASE   = 0x3D000000u;   // below bits(0.05)=0x3D4CCCCD
constexpr int      HB     = 2560;          // (0x3F800000-BASE)>>14
constexpr int      HBPAD  = 3072;          // padded to 1024*3 for the scan
constexpr int      CHUNKB = 3;             // buckets per scan thread
constexpr int      CAP    = 1024;          // candidate capacity

// ---------------- device scratch ----------------
__device__ float    g_scores[Bn * Nn];     // masked score (-FLT_MAX if < THR)
__device__ int      g_labels[Bn * Nn];     // argmax class
__device__ unsigned g_hist[Bn * HBPAD];    // zero-init; re-zeroed by k_select_nms each run

// ---------------- kernel 1: sigmoid + max/argmax + score + fused RED histogram ----------------
// 4 lanes per anchor; each lane reads 20 floats (5x float4), contiguous.
__global__ void k_score(const float* __restrict__ cls,
                        const float* __restrict__ obj) {
    int t   = blockIdx.x * blockDim.x + threadIdx.x;
    int a   = t >> 2;          // anchor
    int sub = t & 3;
    if (a >= Bn * Nn) return;

    const float4* p = reinterpret_cast<const float4*>(cls + (size_t)a * Cc + sub * 20);
    float mx = -FLT_MAX;
    int   mi = 0;
#pragma unroll
    for (int i = 0; i < 5; i++) {
        float4 v = p[i];
        int base = sub * 20 + i * 4;
        if (v.x > mx) { mx = v.x; mi = base; }
        if (v.y > mx) { mx = v.y; mi = base + 1; }
        if (v.z > mx) { mx = v.z; mi = base + 2; }
        if (v.w > mx) { mx = v.w; mi = base + 3; }
    }
#pragma unroll
    for (int off = 1; off < 4; off <<= 1) {
        float om  = __shfl_xor_sync(0xffffffffu, mx, off);
        int   omi = __shfl_xor_sync(0xffffffffu, mi, off);
        if (om > mx || (om == mx && omi < mi)) { mx = om; mi = omi; }
    }
    if (sub == 0) {
        float o = obj[a];
        float s = (1.0f / (1.0f + __expf(-mx))) * (1.0f / (1.0f + __expf(-o)));
        if (s >= THR) {
            unsigned bits = __float_as_uint(s);
            unsigned bk   = (bits - BASE) >> 14;
            if (bk >= (unsigned)HB) bk = HB - 1;
            int batch = a / Nn;
            atomicAdd(&g_hist[batch * HBPAD + bk], 1u);   // RED (no return), chip-wide
            g_scores[a] = s;
        } else {
            g_scores[a] = -FLT_MAX;
        }
        g_labels[a] = mi;
    }
}

// intra-warp inclusive suffix sum (sum over lanes [lane..31])
__device__ __forceinline__ unsigned warp_suffix_sum(unsigned v, int lane) {
#pragma unroll
    for (int o = 1; o < 32; o <<= 1) {
        unsigned u = __shfl_down_sync(0xffffffffu, v, o);
        if (lane + o < 32) v += u;
    }
    return v;
}

// ---------------- kernel 2: scan + rezero + compact + rank + decode + matrix NMS ----------------
__global__ void __launch_bounds__(1024, 1)
k_select_nms(const float* __restrict__ bbox,
             const float* __restrict__ priors,
             float* __restrict__ out,
             int write_keep) {
    __shared__ unsigned           csum[1024];
    __shared__ unsigned           wsum[32];
    __shared__ unsigned long long cand[CAP];
    __shared__ unsigned long long sorted[128];
    __shared__ int                misc[2];
    __shared__ float4             bx4[MAXN];
    __shared__ float              ars[MAXN];
    __shared__ float              sss[MAXN];
    __shared__ int                lls[MAXN];
    __shared__ unsigned           sup[MAXN][4];   // bits r that box-i suppresses
    __shared__ unsigned           kin[4];
    __shared__ unsigned           kout[4];

    int b    = blockIdx.x;
    int tid  = threadIdx.x;
    int lane = tid & 31;
    int wid  = tid >> 5;
    const float* sc = g_scores + (size_t)b * Nn;
    unsigned*    hh = g_hist + b * HBPAD;

    // --- A: chunk sums (3 buckets per thread) ---
    unsigned h0 = hh[tid * CHUNKB + 0];
    unsigned h1 = hh[tid * CHUNKB + 1];
    unsigned h2 = hh[tid * CHUNKB + 2];
    unsigned cs = h0 + h1 + h2;

    // --- B: parallel suffix scan over 1024 chunk sums ---
    unsigned suf = warp_suffix_sum(cs, lane);
    if (lane == 0) wsum[wid] = suf;
    if (tid == 0) misc[0] = 0;
    if (tid < 4) kin[tid] = 0u;
    __syncthreads();
    if (wid == 0) {
        unsigned wv = wsum[lane];
        wsum[lane] = warp_suffix_sum(wv, lane);
    }
    __syncthreads();
    unsigned suffTotal = suf + ((wid < 31) ? wsum[wid + 1] : 0u);
    csum[tid] = suffTotal;
    __syncthreads();

    // boundary chunk: suffix(c) >= MAXN and suffix(c+1) < MAXN
    if (suffTotal >= (unsigned)MAXN &&
        (tid == 1023 || csum[tid + 1] < (unsigned)MAXN))
        misc[0] = tid;
    __syncthreads();

    // --- C: refine to bucket within boundary chunk (<=3 serial steps) ---
    if (tid == 0) {
        int c = misc[0];
        int cum = (c < 1023) ? (int)csum[c + 1] : 0;
        int bstart = c * CHUNKB;
        int bb = bstart + CHUNKB - 1;
        for (; bb >= bstart; bb--) {
            cum += (int)hh[bb];
            if (cum >= MAXN) break;
        }
        misc[0] = (bb < bstart) ? bstart : bb;   // total<MAXN -> take everything
        misc[1] = 0;
    }
    __syncthreads();
    unsigned TB = BASE + ((unsigned)misc[0] << 14);

    // re-zero this batch's histogram for the next graph replay
    hh[tid * CHUNKB + 0] = 0u;
    hh[tid * CHUNKB + 1] = 0u;
    hh[tid * CHUNKB + 2] = 0u;

    // --- D: compact candidates >= bucket boundary (float4 loads) ---
    const float4* sp4 = reinterpret_cast<const float4*>(sc);
#pragma unroll 2
    for (int i = tid; i < Nn / 4; i += 1024) {
        float4 v = sp4[i];
        unsigned bxv = __float_as_uint(v.x);
        unsigned byv = __float_as_uint(v.y);
        unsigned bzv = __float_as_uint(v.z);
        unsigned bwv = __float_as_uint(v.w);
        if (v.x >= THR && bxv >= TB) {
            int pos = atomicAdd(&misc[1], 1);
            if (pos < CAP) cand[pos] = ((unsigned long long)bxv << 32) | (unsigned)(~(4 * i + 0));
        }
        if (v.y >= THR && byv >= TB) {
            int pos = atomicAdd(&misc[1], 1);
            if (pos < CAP) cand[pos] = ((unsigned long long)byv << 32) | (unsigned)(~(4 * i + 1));
        }
        if (v.z >= THR && bzv >= TB) {
            int pos = atomicAdd(&misc[1], 1);
            if (pos < CAP) cand[pos] = ((unsigned long long)bzv << 32) | (unsigned)(~(4 * i + 2));
        }
        if (v.w >= THR && bwv >= TB) {
            int pos = atomicAdd(&misc[1], 1);
            if (pos < CAP) cand[pos] = ((unsigned long long)bwv << 32) | (unsigned)(~(4 * i + 3));
        }
    }
    __syncthreads();
    int cnt = misc[1]; if (cnt > CAP) cnt = CAP;

    // --- E: exact ordering by rank (keys unique: idx in low bits) ---
    if (tid < 128) sorted[tid] = 0ull;
    unsigned long long mykey = 0ull;
    int rank = 0;
    if (tid < cnt) {
        mykey = cand[tid];
#pragma unroll 4
        for (int j = 0; j < cnt; j++) rank += (cand[j] > mykey);
    }
    __syncthreads();
    if (tid < cnt && rank < 128) sorted[rank] = mykey;
    __syncthreads();

    // --- F: decode top-100 ---
    if (tid < MAXN) {
        sup[tid][0] = 0u; sup[tid][1] = 0u; sup[tid][2] = 0u; sup[tid][3] = 0u;
        unsigned long long key = sorted[tid];
        unsigned bits = (unsigned)(key >> 32);
        if (bits != 0u) {
            int idx = (int)(~(unsigned)(key & 0xffffffffu));
            float4 pr = reinterpret_cast<const float4*>(priors)[idx];
            float4 bp = reinterpret_cast<const float4*>(bbox)[(size_t)b * Nn + idx];
            float cx = bp.x * pr.z + pr.x;
            float cy = bp.y * pr.w + pr.y;
            float w  = __expf(bp.z) * pr.z;
            float h  = __expf(bp.w) * pr.w;
            bx4[tid] = make_float4(cx - 0.5f * w, cy - 0.5f * h,
                                   cx + 0.5f * w, cy + 0.5f * h);
            ars[tid] = w * h;
            sss[tid] = __uint_as_float(bits);
            lls[tid] = g_labels[(size_t)b * Nn + idx];
            atomicOr(&kin[tid >> 5], 1u << (tid & 31));
        } else {
            bx4[tid] = make_float4(0.f, 0.f, 0.f, 0.f);
            ars[tid] = 0.f; sss[tid] = 0.f; lls[tid] = -1;
        }
    }
    __syncthreads();

    // --- G: parallel pairwise suppression matrix (r > i, same label, IoU >= thr) ---
    for (int p = tid; p < MAXN * MAXN; p += 1024) {
        int i = p / MAXN;
        int r = p - i * MAXN;
        if (r > i) {
            int li = lls[i];
            if (li >= 0 && li == lls[r]) {
                float4 bi = bx4[i];
                float4 br = bx4[r];
                float ix1 = fmaxf(br.x, bi.x);
                float iy1 = fmaxf(br.y, bi.y);
                float ix2 = fminf(br.z, bi.z);
                float iy2 = fminf(br.w, bi.w);
                float inter = fmaxf(ix2 - ix1, 0.0f) * fmaxf(iy2 - iy1, 0.0f);
                float uni   = ars[i] + ars[r] - inter;
                if (inter / (uni + 1e-8f) >= IOUT)
                    atomicOr(&sup[i][r >> 5], 1u << (r & 31));
            }
        }
    }
    __syncthreads();

    // --- H: greedy scan, pure register bit logic on one thread ---
    if (tid == 0) {
        unsigned k0 = kin[0], k1 = kin[1], k2 = kin[2], k3 = kin[3];
#pragma unroll 4
        for (int i = 0; i < MAXN - 1; i++) {
            unsigned kw = (i < 32) ? k0 : (i < 64) ? k1 : (i < 96) ? k2 : k3;
            if ((kw >> (i & 31)) & 1u) {
                k0 &= ~sup[i][0];
                k1 &= ~sup[i][1];
                k2 &= ~sup[i][2];
                k3 &= ~sup[i][3];
            }
        }
        kout[0] = k0; kout[1] = k1; kout[2] = k2; kout[3] = k3;
    }
    __syncthreads();

    // --- I: write output ---
    if (tid < MAXN) {
        bool kept = (kout[tid >> 5] >> (tid & 31)) & 1u;
        float* row = out + ((size_t)b * MAXN + tid) * 6;
        if (kept) {
            float4 bb = bx4[tid];
            row[0] = bb.x; row[1] = bb.y; row[2] = bb.z; row[3] = bb.w;
            row[4] = sss[tid]; row[5] = (float)lls[tid];
        } else {
            row[0] = 0.0f; row[1] = 0.0f; row[2] = 0.0f; row[3] = 0.0f;
            row[4] = 0.0f; row[5] = -1.0f;
        }
        if (write_keep)
            out[(size_t)Bn * MAXN * 6 + b * MAXN + tid] = kept ? 1.0f : 0.0f;
    }
}

// ---------------- host launcher ----------------
extern "C" void kernel_launch(void* const* d_in, const int* in_sizes, int n_in,
                              void* d_out, int out_size) {
    const float* cls    = nullptr;
    const float* bbox   = nullptr;
    const float* obj    = nullptr;
    const float* priors = nullptr;
    for (int i = 0; i < n_in; i++) {
        int sz = in_sizes[i];
        if      (sz == Bn * Nn * Cc) cls    = (const float*)d_in[i];
        else if (sz == Bn * Nn * 4)  bbox   = (const float*)d_in[i];
        else if (sz == Bn * Nn)      obj    = (const float*)d_in[i];
        else if (sz == Nn * 4)       priors = (const float*)d_in[i];
    }
    float* out = (float*)d_out;
    int write_keep = (out_size >= Bn * MAXN * 6 + Bn * MAXN) ? 1 : 0;

    int total_threads = Bn * Nn * 4;
    k_score<<<(total_threads + 255) / 256, 256>>>(cls, obj);
    k_select_nms<<<Bn, 1024>>>(bbox, priors, out, write_keep);
}